// round 2
// baseline (speedup 1.0000x reference)
#include <cuda_runtime.h>

#define D      128     // feature dim (rank*nc)
#define U      256     // n_units
#define KC     10      // candidates per spike
#define GRID_B 148     // one CTA per SM
#define WARPS  8
#define SPB    4       // spikes per warp per round
#define ROW    132     // padded stats row (16B-aligned), col 128 = count

__device__ __align__(16) float g_w[U * D];      // inv_var * mu
__device__ float g_b[U];                        // -0.5*sum(inv_var*mu^2) + log_prop
__device__ float g_part[GRID_B * U * (D + 1)];  // per-CTA partial stats
__device__ int   g_c64;                         // 1 if candidates are int64

// ---------------- probe: detect candidate dtype ----------------
// Candidate values are in [0, 256). If the buffer is little-endian int64,
// every odd 32-bit word is zero. If int32, odd words are random candidates.
__global__ void probe_kernel(const int* __restrict__ c, int nwords) {
    __shared__ int any;
    if (threadIdx.x == 0) any = 0;
    __syncthreads();
    for (int i = threadIdx.x * 2 + 1; i < nwords; i += 512)
        if (c[i] != 0) any = 1;
    __syncthreads();
    if (threadIdx.x == 0) g_c64 = (any == 0) ? 1 : 0;
}

// ---------------- prep: build w, b ----------------
__global__ void prep_kernel(const float* __restrict__ means,
                            const float* __restrict__ lnv,
                            const float* __restrict__ lp) {
    int u = blockIdx.x;
    int d = threadIdx.x;            // 128 threads
    float iv = expf(-lnv[d]);
    float m  = means[u * D + d];
    float wv = iv * m;
    g_w[u * D + d] = wv;
    float p = wv * m;
    #pragma unroll
    for (int o = 16; o; o >>= 1) p += __shfl_xor_sync(0xffffffffu, p, o);
    __shared__ float red[4];
    if ((threadIdx.x & 31) == 0) red[threadIdx.x >> 5] = p;
    __syncthreads();
    if (threadIdx.x == 0) {
        float s = red[0] + red[1] + red[2] + red[3];
        g_b[u] = -0.5f * s + lp[u];
    }
}

// ---------------- main E-step ----------------
__global__ void __launch_bounds__(WARPS * 32, 1)
estep_kernel(const float* __restrict__ x,
             const int* __restrict__ candw,   // candidate buffer as 32-bit words
             int n, int chunk) {
    extern __shared__ float sm[];
    float* stats = sm;                               // U*ROW floats
    int*   se_u  = (int*)(sm + U * ROW);             // WARPS*SPB*KC
    float* se_r  = (float*)(se_u + WARPS * SPB * KC);

    const int tid  = threadIdx.x;
    const int lane = tid & 31;
    const int w    = tid >> 5;
    const int s64  = g_c64;                          // 0: int32, 1: int64

    // zero stats
    for (int i = tid; i < (U * ROW) / 4; i += WARPS * 32)
        ((float4*)stats)[i] = make_float4(0.f, 0.f, 0.f, 0.f);
    __syncthreads();

    const int base = blockIdx.x * chunk;
    const int end  = (base + chunk < n) ? (base + chunk) : n;
    const int per_round = WARPS * SPB;
    const int rounds = (chunk + per_round - 1) / per_round;

    for (int rd = 0; rd < rounds; rd++) {
        float4 xs[SPB];

        // ---- phase 1: logits + softmax for SPB spikes per warp ----
        #pragma unroll
        for (int s = 0; s < SPB; s++) {
            int nidx  = base + rd * per_round + w * SPB + s;
            bool valid = (nidx < end);
            float4 x4 = valid ? ((const float4*)x)[(size_t)nidx * 32 + lane]
                              : make_float4(0.f, 0.f, 0.f, 0.f);
            xs[s] = x4;

            int myu = U;  // U == invalid marker (group 8 never matches)
            if (valid && lane < KC)
                myu = candw[((size_t)nidx * KC + lane) << s64];

            float logits[KC];
            float mylogit = 0.f;
            #pragma unroll
            for (int k = 0; k < KC; k++) {
                int u = __shfl_sync(0xffffffffu, myu, k);
                float dot = 0.f;
                float bu  = 0.f;
                if (u < U) {  // warp-uniform branch
                    float4 w4 = ((const float4*)g_w)[u * 32 + lane];
                    dot = w4.x * x4.x + w4.y * x4.y + w4.z * x4.z + w4.w * x4.w;
                    bu  = g_b[u];
                }
                #pragma unroll
                for (int o = 16; o; o >>= 1)
                    dot += __shfl_xor_sync(0xffffffffu, dot, o);
                float lg = dot + bu;
                logits[k] = lg;
                if (lane == k) mylogit = lg;
            }

            // softmax over 10 logits + noise const (-2.0); all lanes identical
            float mx = -2.0f;
            #pragma unroll
            for (int k = 0; k < KC; k++) mx = fmaxf(mx, logits[k]);
            float ssum = __expf(-2.0f - mx);
            #pragma unroll
            for (int k = 0; k < KC; k++) ssum += __expf(logits[k] - mx);
            float inv = 1.f / ssum;

            if (lane < KC) {
                se_u[(w * SPB + s) * KC + lane] = myu;
                se_r[(w * SPB + s) * KC + lane] = __expf(mylogit - mx) * inv;
            }
        }

        // ---- phase 2: race-free scatter via rotating unit-group ownership ----
        #pragma unroll 1
        for (int r = 0; r < WARPS; r++) {
            __syncthreads();
            int g = (w + r) & 7;
            #pragma unroll
            for (int s = 0; s < SPB; s++) {
                #pragma unroll
                for (int k = 0; k < KC; k++) {
                    int u = se_u[(w * SPB + s) * KC + k];  // smem broadcast
                    if ((u >> 5) == g) {
                        float rv = se_r[(w * SPB + s) * KC + k];
                        float4* row = (float4*)(stats + u * ROW);
                        float4 f4 = row[lane];
                        float4 x4 = xs[s];
                        f4.x += rv * x4.x;
                        f4.y += rv * x4.y;
                        f4.z += rv * x4.z;
                        f4.w += rv * x4.w;
                        row[lane] = f4;
                        if (lane == 0) stats[u * ROW + 128] += rv;
                    }
                }
            }
        }
    }
    __syncthreads();

    // flush partials (plain STG, no atomics)
    const int c = blockIdx.x;
    for (int i = tid; i < U * (D + 1); i += WARPS * 32) {
        int u = i / (D + 1);
        int d = i - u * (D + 1);
        g_part[c * (U * (D + 1)) + i] = stats[u * ROW + d];
    }
}

// ---------------- final reduction over CTA partials ----------------
__global__ void reduce_kernel(float* __restrict__ out) {
    int i = blockIdx.x * blockDim.x + threadIdx.x;
    if (i < U * (D + 1)) {
        float s = 0.f;
        #pragma unroll 4
        for (int p = 0; p < GRID_B; p++)
            s += g_part[p * (U * (D + 1)) + i];
        out[i] = s;
    }
}

extern "C" void kernel_launch(void* const* d_in, const int* in_sizes, int n_in,
                              void* d_out, int out_size) {
    const float* feats = (const float*)d_in[0];
    const float* means = (const float*)d_in[1];
    const float* lnv   = (const float*)d_in[2];
    const float* lp    = (const float*)d_in[3];
    const int*   candw = (const int*)d_in[4];

    int n  = in_sizes[0] / D;    // number of spikes
    int nK = in_sizes[4];        // n * K elements (any dtype)

    int probe_words = nK < 4096 ? nK : 4096;  // safe under either dtype
    probe_kernel<<<1, 256>>>(candw, probe_words);

    prep_kernel<<<U, D>>>(means, lnv, lp);

    int chunk = (n + GRID_B - 1) / GRID_B;
    size_t smem = (size_t)U * ROW * sizeof(float)
                + (size_t)WARPS * SPB * KC * (sizeof(int) + sizeof(float));
    cudaFuncSetAttribute(estep_kernel,
                         cudaFuncAttributeMaxDynamicSharedMemorySize,
                         (int)smem);
    estep_kernel<<<GRID_B, WARPS * 32, smem>>>(feats, candw, n, chunk);

    int total = U * (D + 1);
    reduce_kernel<<<(total + 255) / 256, 256>>>((float*)d_out);
}

// round 3
// speedup vs baseline: 2.4527x; 2.4527x over previous
#include <cuda_runtime.h>

#define D        128
#define U        256
#define KC       10
#define GRID_B   148
#define NMAX     131072
#define WB       16            // warps in scatter kernel / buckets
#define SPW      4             // spikes per warp per round
#define SROUND   (WB * SPW)    // 64 spikes staged per round
#define ROW      132           // padded row (528B, 16B-aligned)
#define THREADS_B (WB * 32)

__device__ __align__(16) float g_w[U * D];       // inv_var * mu  (128 KB)
__device__ float g_b[U];
__device__ float g_resp[(size_t)NMAX * KC];      // responsibilities scratch
__device__ float g_part[GRID_B * U * (D + 1)];   // per-CTA partial stats
__device__ int   g_c64;

// ---------------- probe: candidate dtype (int64 -> odd words all zero) ----
__global__ void probe_kernel(const int* __restrict__ c, int nwords) {
    __shared__ int any;
    if (threadIdx.x == 0) any = 0;
    __syncthreads();
    for (int i = threadIdx.x * 2 + 1; i < nwords; i += 512)
        if (c[i] != 0) any = 1;
    __syncthreads();
    if (threadIdx.x == 0) g_c64 = (any == 0) ? 1 : 0;
}

// ---------------- prep ----------------------------------------------------
__global__ void prep_kernel(const float* __restrict__ means,
                            const float* __restrict__ lnv,
                            const float* __restrict__ lp) {
    int u = blockIdx.x, d = threadIdx.x;
    float iv = expf(-lnv[d]);
    float m  = means[u * D + d];
    float wv = iv * m;
    g_w[u * D + d] = wv;
    float p = wv * m;
    #pragma unroll
    for (int o = 16; o; o >>= 1) p += __shfl_xor_sync(0xffffffffu, p, o);
    __shared__ float red[4];
    if ((threadIdx.x & 31) == 0) red[threadIdx.x >> 5] = p;
    __syncthreads();
    if (threadIdx.x == 0) g_b[u] = -0.5f * (red[0] + red[1] + red[2] + red[3]) + lp[u];
}

// ---------------- kernel A: logits + softmax -> resp ----------------------
__global__ void __launch_bounds__(512, 1)
resp_kernel(const float* __restrict__ x, const int* __restrict__ candw, int n) {
    const int lane = threadIdx.x & 31;
    const int gw   = (blockIdx.x * blockDim.x + threadIdx.x) >> 5;
    const int nw   = (gridDim.x * blockDim.x) >> 5;
    const int s64  = g_c64;

    for (int s = gw; s < n; s += nw) {
        float4 x4 = __ldcs((const float4*)x + (size_t)s * 32 + lane);
        int myu = U;
        if (lane < KC) myu = __ldcs(&candw[((size_t)s * KC + lane) << s64]);

        float logits[KC];
        float mylogit = 0.f;
        #pragma unroll
        for (int k = 0; k < KC; k++) {
            int u = __shfl_sync(0xffffffffu, myu, k);
            float dot = 0.f, bu = 0.f;
            if ((unsigned)u < U) {
                float4 w4 = ((const float4*)g_w)[u * 32 + lane];
                dot = fmaf(w4.x, x4.x, fmaf(w4.y, x4.y, fmaf(w4.z, x4.z, w4.w * x4.w)));
                bu  = g_b[u];
            }
            #pragma unroll
            for (int o = 16; o; o >>= 1)
                dot += __shfl_xor_sync(0xffffffffu, dot, o);
            float lg = dot + bu;
            logits[k] = lg;
            if (lane == k) mylogit = lg;
        }
        float mx = -2.0f;
        #pragma unroll
        for (int k = 0; k < KC; k++) mx = fmaxf(mx, logits[k]);
        float ssum = __expf(-2.0f - mx);
        #pragma unroll
        for (int k = 0; k < KC; k++) ssum += __expf(logits[k] - mx);
        float inv = 1.f / ssum;
        if (lane < KC)
            __stcs(&g_resp[(size_t)s * KC + lane], __expf(mylogit - mx) * inv);
    }
}

// ---------------- kernel B: bucketed scatter into smem stats --------------
__global__ void __launch_bounds__(THREADS_B, 1)
scatter_kernel(const float* __restrict__ x, const int* __restrict__ candw,
               int n, int chunk) {
    extern __shared__ float sm[];
    float* stats = sm;                                  // U*ROW floats
    float* xs    = sm + U * ROW;                        // SROUND*ROW floats
    int2*  ent   = (int2*)(xs + SROUND * ROW);          // SROUND*KC entries
    int*   cnt   = (int*)(ent + SROUND * KC);           // WB counters
    int*   offs  = cnt + WB;                            // WB+1 (incl. total)

    const int tid = threadIdx.x, lane = tid & 31, w = tid >> 5;
    const int s64 = g_c64;

    for (int i = tid; i < (U * ROW) / 4; i += THREADS_B)
        ((float4*)stats)[i] = make_float4(0.f, 0.f, 0.f, 0.f);
    if (tid < WB) cnt[tid] = 0;
    __syncthreads();

    const int base = blockIdx.x * chunk;
    const int end  = (base + chunk < n) ? (base + chunk) : n;

    for (int rb = base; rb < end; rb += SROUND) {
        // ---- stage x tiles + histogram ----
        int g[SPW], slot[SPW], uu[SPW];
        float rr[SPW];
        #pragma unroll
        for (int j = 0; j < SPW; j++) {
            g[j] = -1;
            int sl = w * SPW + j;
            int s  = rb + sl;
            if (s < end) {
                float4 x4 = __ldcs((const float4*)x + (size_t)s * 32 + lane);
                ((float4*)(xs + sl * ROW))[lane] = x4;
                if (lane < KC) {
                    int u = __ldcs(&candw[((size_t)s * KC + lane) << s64]);
                    if ((unsigned)u < U) {
                        float r = __ldcs(&g_resp[(size_t)s * KC + lane]);
                        uu[j] = u; rr[j] = r; g[j] = u >> 4;
                        slot[j] = atomicAdd(&cnt[g[j]], 1);
                    }
                }
            }
        }
        __syncthreads();
        // ---- exclusive prefix over bucket counts (warp 0); offs[WB]=total -
        if (w == 0 && lane < WB) {
            int c = cnt[lane], sc = c;
            #pragma unroll
            for (int o = 1; o < WB; o <<= 1) {
                int v = __shfl_up_sync(0xffffu, sc, o);
                if (lane >= o) sc += v;
            }
            offs[lane] = sc - c;
            if (lane == WB - 1) offs[WB] = sc;
        }
        __syncthreads();
        // ---- scatter entries into compact bucket segments ----
        #pragma unroll
        for (int j = 0; j < SPW; j++) {
            if (g[j] >= 0) {
                int2 e;
                e.x = uu[j] | ((w * SPW + j) << 16);
                e.y = __float_as_int(rr[j]);
                ent[offs[g[j]] + slot[j]] = e;
            }
        }
        if (tid < WB) cnt[tid] = 0;     // safe: cnt not read again this round
        __syncthreads();
        // ---- warp w drains bucket w (race-free by ownership) ----
        {
            int beg  = offs[w];
            int cend = offs[w + 1];
            #pragma unroll 2
            for (int i = beg; i < cend; i++) {
                int2 e = ent[i];
                int u  = e.x & 0xffff;
                int sl = e.x >> 16;
                float r = __int_as_float(e.y);
                float4 xv = ((const float4*)(xs + sl * ROW))[lane];
                float4* rowp = (float4*)(stats + u * ROW);
                float4 f = rowp[lane];
                f.x = fmaf(r, xv.x, f.x);
                f.y = fmaf(r, xv.y, f.y);
                f.z = fmaf(r, xv.z, f.z);
                f.w = fmaf(r, xv.w, f.w);
                rowp[lane] = f;
                if (lane == 0) stats[u * ROW + 128] += r;
            }
        }
        __syncthreads();
    }

    for (int i = tid; i < U * (D + 1); i += THREADS_B) {
        int u = i / (D + 1);
        int d = i - u * (D + 1);
        g_part[blockIdx.x * (U * (D + 1)) + i] = stats[u * ROW + d];
    }
}

// ---------------- final reduction (MLP-deep) -------------------------------
__global__ void reduce_kernel(float* __restrict__ out) {
    int i = blockIdx.x * blockDim.x + threadIdx.x;
    if (i < U * (D + 1)) {
        float s0 = 0.f, s1 = 0.f, s2 = 0.f, s3 = 0.f;
        #pragma unroll 2
        for (int p = 0; p < GRID_B; p += 4) {
            s0 += g_part[(p + 0) * (U * (D + 1)) + i];
            s1 += g_part[(p + 1) * (U * (D + 1)) + i];
            s2 += g_part[(p + 2) * (U * (D + 1)) + i];
            s3 += g_part[(p + 3) * (U * (D + 1)) + i];
        }
        out[i] = (s0 + s1) + (s2 + s3);
    }
}

extern "C" void kernel_launch(void* const* d_in, const int* in_sizes, int n_in,
                              void* d_out, int out_size) {
    const float* feats = (const float*)d_in[0];
    const float* means = (const float*)d_in[1];
    const float* lnv   = (const float*)d_in[2];
    const float* lp    = (const float*)d_in[3];
    const int*   candw = (const int*)d_in[4];

    int n  = in_sizes[0] / D;
    int nK = in_sizes[4];
    int probe_words = nK < 4096 ? nK : 4096;

    probe_kernel<<<1, 256>>>(candw, probe_words);
    prep_kernel<<<U, D>>>(means, lnv, lp);

    resp_kernel<<<GRID_B, 512>>>(feats, candw, n);

    int chunk = (n + GRID_B - 1) / GRID_B;
    size_t smem = (size_t)U * ROW * sizeof(float)
                + (size_t)SROUND * ROW * sizeof(float)
                + (size_t)SROUND * KC * sizeof(int2)
                + (2 * WB + 4) * sizeof(int);
    cudaFuncSetAttribute(scatter_kernel,
                         cudaFuncAttributeMaxDynamicSharedMemorySize, (int)smem);
    scatter_kernel<<<GRID_B, THREADS_B, smem>>>(feats, candw, n, chunk);

    int total = U * (D + 1);
    reduce_kernel<<<(total + 255) / 256, 256>>>((float*)d_out);
}

// round 5
// speedup vs baseline: 2.4684x; 1.0064x over previous
#include <cuda_runtime.h>

#define D         128
#define U         256
#define KC        10
#define GRID_B    148
#define NMAX      131072
#define WB        16             // warps in scatter kernel
#define SPW       8              // spikes per warp per round
#define SROUND    128            // spikes staged per round
#define ROW       132            // stats row stride (floats)
#define XROW      128            // staged x row stride (floats)
#define THREADS_B (WB * 32)

__device__ __align__(16) float g_w[U * D];       // inv_var * mu  (128 KB)
__device__ float g_b[U];
__device__ float g_resp[(size_t)NMAX * KC];
__device__ float g_part[GRID_B * U * (D + 1)];
__device__ int   g_c64;

__device__ __forceinline__ unsigned smem_u32(const void* p) {
    return (unsigned)__cvta_generic_to_shared(p);
}

// ---------------- prep (+ dtype probe in block 0) ---------------------------
__global__ void prep_kernel(const float* __restrict__ means,
                            const float* __restrict__ lnv,
                            const float* __restrict__ lp,
                            const int* __restrict__ candw, int probe_words) {
    int u = blockIdx.x, d = threadIdx.x;
    float iv = expf(-lnv[d]);
    float m  = means[u * D + d];
    float wv = iv * m;
    g_w[u * D + d] = wv;
    float p = wv * m;
    #pragma unroll
    for (int o = 16; o; o >>= 1) p += __shfl_xor_sync(0xffffffffu, p, o);
    __shared__ float red[4];
    __shared__ int any;
    if (threadIdx.x == 0) any = 0;
    if ((threadIdx.x & 31) == 0) red[threadIdx.x >> 5] = p;
    __syncthreads();
    if (threadIdx.x == 0)
        g_b[u] = -0.5f * (red[0] + red[1] + red[2] + red[3]) + lp[u];
    if (blockIdx.x == 0) {
        // int64 little-endian -> all odd 32-bit words are zero
        for (int i = threadIdx.x * 2 + 1; i < probe_words; i += 2 * D)
            if (candw[i] != 0) any = 1;
        __syncthreads();
        if (threadIdx.x == 0) g_c64 = (any == 0) ? 1 : 0;
    }
}

// ---------------- kernel A: logits + softmax -> resp ------------------------
// 8-lane slices: lane = 8*g + i; slice g handles candidate k = 4*p + g in
// pass p; lane i covers dims [16i, 16i+16). 16 shuffles/spike total.
__global__ void __launch_bounds__(512, 1)
resp_kernel(const float* __restrict__ x, const int* __restrict__ candw, int n) {
    const int lane = threadIdx.x & 31;
    const int g    = lane >> 3;
    const int i    = lane & 7;
    const int gw   = (blockIdx.x * blockDim.x + threadIdx.x) >> 5;
    const int nw   = (gridDim.x * blockDim.x) >> 5;
    const int s64  = g_c64;

    for (int s = gw; s < n; s += nw) {
        const float4* xr = (const float4*)x + (size_t)s * 32 + 4 * i;
        float4 xa0 = __ldcs(xr + 0);
        float4 xa1 = __ldcs(xr + 1);
        float4 xa2 = __ldcs(xr + 2);
        float4 xa3 = __ldcs(xr + 3);

        int myu = 0;
        if (lane < KC) myu = __ldcs(&candw[((size_t)s * KC + lane) << s64]);

        float lg[3];
        #pragma unroll
        for (int p = 0; p < 3; p++) {
            int  k  = 4 * p + g;
            bool kv = (k < KC);
            int  u  = __shfl_sync(0xffffffffu, myu, kv ? k : 0);
            const float4* wr = (const float4*)g_w + u * 32 + 4 * i;
            float4 w0 = wr[0], w1 = wr[1], w2 = wr[2], w3 = wr[3];
            float dot =
                fmaf(w0.x, xa0.x, fmaf(w0.y, xa0.y, fmaf(w0.z, xa0.z,
                fmaf(w0.w, xa0.w, fmaf(w1.x, xa1.x, fmaf(w1.y, xa1.y,
                fmaf(w1.z, xa1.z, fmaf(w1.w, xa1.w, fmaf(w2.x, xa2.x,
                fmaf(w2.y, xa2.y, fmaf(w2.z, xa2.z, fmaf(w2.w, xa2.w,
                fmaf(w3.x, xa3.x, fmaf(w3.y, xa3.y, fmaf(w3.z, xa3.z,
                     w3.w * xa3.w)))))))))))))));
            dot += __shfl_xor_sync(0xffffffffu, dot, 4);
            dot += __shfl_xor_sync(0xffffffffu, dot, 2);
            dot += __shfl_xor_sync(0xffffffffu, dot, 1);
            lg[p] = kv ? dot + __ldg(&g_b[u]) : -1e30f;
        }

        // global max over 10 logits + noise(-2): butterfly across groups
        float m = fmaxf(fmaxf(lg[0], lg[1]), fmaxf(lg[2], -2.0f));
        m = fmaxf(m, __shfl_xor_sync(0xffffffffu, m, 8));
        m = fmaxf(m, __shfl_xor_sync(0xffffffffu, m, 16));

        float e0 = __expf(lg[0] - m);
        float e1 = __expf(lg[1] - m);
        float e2 = __expf(lg[2] - m);
        float sl = e0 + e1 + e2;   // per-group partial (identical in 8 lanes)
        // offsets 8,16 combine exactly one lane per group -> no duplication
        sl += __shfl_xor_sync(0xffffffffu, sl, 8);
        sl += __shfl_xor_sync(0xffffffffu, sl, 16);
        float inv = 1.f / (sl + __expf(-2.0f - m));

        if (i < 3) {
            int k = 4 * i + g;
            if (k < KC) {
                float e = (i == 0) ? e0 : ((i == 1) ? e1 : e2);
                __stcs(&g_resp[(size_t)s * KC + k], e * inv);
            }
        }
    }
}

// ---------------- kernel B: per-unit bucketed scatter -----------------------
__global__ void __launch_bounds__(THREADS_B, 1)
scatter_kernel(const float* __restrict__ x, const int* __restrict__ candw,
               int n, int chunk) {
    extern __shared__ float sm[];
    float* stats = sm;                                   // U*ROW
    float* xs    = sm + U * ROW;                         // SROUND*XROW
    int2*  ent   = (int2*)(xs + SROUND * XROW);          // SROUND*KC
    int*   cnt   = (int*)(ent + SROUND * KC);            // U
    int*   offs  = cnt + U;                              // U+1
    int*   wtot  = offs + U + 1;                         // WB
    int*   wbase = wtot + WB;                            // WB

    const int tid = threadIdx.x, lane = tid & 31, w = tid >> 5;
    const int s64 = g_c64;

    for (int i = tid; i < (U * ROW) / 4; i += THREADS_B)
        ((float4*)stats)[i] = make_float4(0.f, 0.f, 0.f, 0.f);
    for (int i = tid; i < U; i += THREADS_B) cnt[i] = 0;
    __syncthreads();

    const int base = blockIdx.x * chunk;
    const int end  = (base + chunk < n) ? (base + chunk) : n;

    for (int rb = base; rb < end; rb += SROUND) {
        // ---- issue async x tile copies (gmem -> smem, bypass L1) ----
        #pragma unroll
        for (int j = 0; j < SPW; j++) {
            int sl = w * SPW + j;
            int s  = rb + sl;
            if (s < end) {
                unsigned dst = smem_u32(xs + sl * XROW + lane * 4);
                const float* src = x + (size_t)s * D + lane * 4;
                asm volatile("cp.async.cg.shared.global [%0], [%1], 16;\n"
                             :: "r"(dst), "l"(src));
            }
        }
        asm volatile("cp.async.commit_group;\n");

        // ---- candidates + resp + per-unit histogram (overlaps copies) ----
        int uu[SPW], slot[SPW];
        float rr[SPW];
        #pragma unroll
        for (int j = 0; j < SPW; j++) {
            uu[j] = -1;
            int s = rb + w * SPW + j;
            if (s < end && lane < KC) {
                int u = __ldcs(&candw[((size_t)s * KC + lane) << s64]);
                if ((unsigned)u < U) {
                    uu[j] = u;
                    rr[j] = __ldcs(&g_resp[(size_t)s * KC + lane]);
                    slot[j] = atomicAdd(&cnt[u], 1);
                }
            }
        }
        __syncthreads();                                  // cnt complete

        // ---- two-level exclusive scan over 256 counts ----
        int c = 0;
        if (lane < 16) c = cnt[w * 16 + lane];
        int sc = c;
        #pragma unroll
        for (int o = 1; o < 16; o <<= 1) {
            int v = __shfl_up_sync(0xffffffffu, sc, o);
            if (lane >= o && lane < 16) sc += v;
        }
        if (lane == 15) wtot[w] = sc;
        __syncthreads();                                  // wtot ready
        if (tid < U) cnt[tid] = 0;                        // reset for next rd
        if (w == 0) {
            int t = (lane < 16) ? wtot[lane] : 0;
            int st = t;
            #pragma unroll
            for (int o = 1; o < 16; o <<= 1) {
                int v = __shfl_up_sync(0xffffffffu, st, o);
                if (lane >= o && lane < 16) st += v;
            }
            if (lane < 16) wbase[lane] = st - t;
            if (lane == 15) offs[U] = st;
        }
        __syncthreads();                                  // wbase ready
        if (lane < 16) offs[w * 16 + lane] = wbase[w] + sc - c;
        __syncthreads();                                  // offs ready

        // ---- compact entries into per-unit segments ----
        #pragma unroll
        for (int j = 0; j < SPW; j++) {
            if (uu[j] >= 0) {
                int2 e;
                e.x = w * SPW + j;                // spike slot in xs
                e.y = __float_as_int(rr[j]);
                ent[offs[uu[j]] + slot[j]] = e;
            }
        }
        asm volatile("cp.async.wait_group 0;\n" ::: "memory");
        __syncthreads();                                  // ent + xs ready

        // ---- warp w drains its 16 units: one row RMW per touched unit ----
        #pragma unroll 1
        for (int u = w * 16; u < w * 16 + 16; u++) {
            int beg = offs[u], e_ = offs[u + 1];
            if (beg >= e_) continue;
            float4* rowp = (float4*)(stats + u * ROW);
            float4 f = rowp[lane];
            float csum = 0.f;
            #pragma unroll 2
            for (int i = beg; i < e_; i++) {
                int2 e = ent[i];
                float r = __int_as_float(e.y);
                float4 xv = ((const float4*)(xs + e.x * XROW))[lane];
                f.x = fmaf(r, xv.x, f.x);
                f.y = fmaf(r, xv.y, f.y);
                f.z = fmaf(r, xv.z, f.z);
                f.w = fmaf(r, xv.w, f.w);
                csum += r;
            }
            rowp[lane] = f;
            if (lane == 0) stats[u * ROW + 128] += csum;
        }
        __syncthreads();                                  // xs/ent reusable
    }

    for (int i = tid; i < U * (D + 1); i += THREADS_B) {
        int u = i / (D + 1);
        int d = i - u * (D + 1);
        g_part[blockIdx.x * (U * (D + 1)) + i] = stats[u * ROW + d];
    }
}

// ---------------- final reduction: 64 outputs x 4 slices per block ----------
__global__ void reduce_kernel(float* __restrict__ out) {
    __shared__ float red[4][64];
    const int ol    = threadIdx.x & 63;
    const int slice = threadIdx.x >> 6;          // 0..3
    const int o     = blockIdx.x * 64 + ol;
    const int pb    = slice * 37;
    const int pe    = (pb + 37 < GRID_B) ? pb + 37 : GRID_B;
    float s0 = 0.f, s1 = 0.f, s2 = 0.f, s3 = 0.f;
    int p = pb;
    for (; p + 4 <= pe; p += 4) {
        s0 += g_part[(p + 0) * (U * (D + 1)) + o];
        s1 += g_part[(p + 1) * (U * (D + 1)) + o];
        s2 += g_part[(p + 2) * (U * (D + 1)) + o];
        s3 += g_part[(p + 3) * (U * (D + 1)) + o];
    }
    for (; p < pe; p++) s0 += g_part[p * (U * (D + 1)) + o];
    red[slice][ol] = (s0 + s1) + (s2 + s3);
    __syncthreads();
    if (slice == 0)
        out[o] = (red[0][ol] + red[1][ol]) + (red[2][ol] + red[3][ol]);
}

extern "C" void kernel_launch(void* const* d_in, const int* in_sizes, int n_in,
                              void* d_out, int out_size) {
    const float* feats = (const float*)d_in[0];
    const float* means = (const float*)d_in[1];
    const float* lnv   = (const float*)d_in[2];
    const float* lp    = (const float*)d_in[3];
    const int*   candw = (const int*)d_in[4];

    int n  = in_sizes[0] / D;
    int nK = in_sizes[4];
    int probe_words = nK < 4096 ? nK : 4096;

    prep_kernel<<<U, D>>>(means, lnv, lp, candw, probe_words);
    resp_kernel<<<GRID_B, 512>>>(feats, candw, n);

    int chunk = (n + GRID_B - 1) / GRID_B;
    size_t smem = (size_t)U * ROW * sizeof(float)
                + (size_t)SROUND * XROW * sizeof(float)
                + (size_t)SROUND * KC * sizeof(int2)
                + (size_t)(U + (U + 1) + WB + WB) * sizeof(int);
    cudaFuncSetAttribute(scatter_kernel,
                         cudaFuncAttributeMaxDynamicSharedMemorySize, (int)smem);
    scatter_kernel<<<GRID_B, THREADS_B, smem>>>(feats, candw, n, chunk);

    reduce_kernel<<<(U * (D + 1)) / 64, 256>>>((float*)d_out);
}